// round 11
// baseline (speedup 1.0000x reference)
#include <cuda_runtime.h>
#include <cuda_fp16.h>
#include <cstdint>
#include <math.h>

#define D        10
#define NUMF     16
#define DIN      36
#define H        128
#define CS1      1
#define CS2      3
#define TILE_M   128
#define THREADS  128

#define E1_TOK (TILE_M + 2*CS1)   // 130
#define E2_TOK (TILE_M + 2*CS2)   // 134
#define NROWS  (E1_TOK + E2_TOK)  // 264 combined gather rows
#define KW     20
#define PW     136                 // plane stride: 136 % 32 == 8 -> conflict-free frags
#define VOCAB_MAX 65536

// fp16 tables: row = 16 halves (10 used) = 32B
__device__ uint4 g_T1h[VOCAB_MAX * 2];
__device__ uint4 g_T2h[VOCAB_MAX * 2];

__device__ __forceinline__ uint32_t h2pair(float a, float b) {
    __half2 h = __floats2half2_rn(a, b);
    return *reinterpret_cast<uint32_t*>(&h);
}

__global__ void convert_tables_kernel(const float* __restrict__ T1,
                                      const float* __restrict__ T2, int vocab) {
    int idx = blockIdx.x * blockDim.x + threadIdx.x;
    int total = vocab * 2;
    for (int e = idx; e < total; e += gridDim.x * blockDim.x) {
        int r = e >> 1, hf = e & 1;
        const float* r1 = T1 + r * D;
        const float* r2 = T2 + r * D;
        uint4 v1, v2;
        if (hf == 0) {
            v1.x = h2pair(r1[0], r1[1]); v1.y = h2pair(r1[2], r1[3]);
            v1.z = h2pair(r1[4], r1[5]); v1.w = h2pair(r1[6], r1[7]);
            v2.x = h2pair(r2[0], r2[1]); v2.y = h2pair(r2[2], r2[3]);
            v2.z = h2pair(r2[4], r2[5]); v2.w = h2pair(r2[6], r2[7]);
        } else {
            v1.x = h2pair(r1[8], r1[9]); v1.y = 0u; v1.z = 0u; v1.w = 0u;
            v2.x = h2pair(r2[8], r2[9]); v2.y = 0u; v2.z = 0u; v2.w = 0u;
        }
        g_T1h[e] = v1;
        g_T2h[e] = v2;
    }
}

__device__ __forceinline__ void mma16(float d[4],
                                      uint32_t a0, uint32_t a1, uint32_t a2, uint32_t a3,
                                      uint32_t b0, uint32_t b1) {
    asm volatile(
        "mma.sync.aligned.m16n8k16.row.col.f32.f16.f16.f32 "
        "{%0,%1,%2,%3}, {%4,%5,%6,%7}, {%8,%9}, {%0,%1,%2,%3};"
        : "+f"(d[0]), "+f"(d[1]), "+f"(d[2]), "+f"(d[3])
        : "r"(a0), "r"(a1), "r"(a2), "r"(a3), "r"(b0), "r"(b1));
}
__device__ __forceinline__ void mma8(float d[4], uint32_t a0, uint32_t a1, uint32_t b0) {
    asm volatile(
        "mma.sync.aligned.m16n8k8.row.col.f32.f16.f16.f32 "
        "{%0,%1,%2,%3}, {%4,%5}, {%6}, {%0,%1,%2,%3};"
        : "+f"(d[0]), "+f"(d[1]), "+f"(d[2]), "+f"(d[3])
        : "r"(a0), "r"(a1), "r"(b0));
}

__global__ __launch_bounds__(THREADS, 6)
void wordemb_wf_kernel(
    const int*   __restrict__ t1,
    const int*   __restrict__ t2,
    const float* __restrict__ numf,
    const float* __restrict__ W1,
    const float* __restrict__ b1,
    const float* __restrict__ W2,
    const float* __restrict__ b2,
    float* __restrict__ out,
    int n, int nTiles)
{
    __shared__ uint32_t s_A[KW * PW];
    __shared__ uint32_t s_e1[E1_TOK * 5];
    __shared__ uint32_t s_e2[E2_TOK * 5];
    __shared__ int   s_tk1[2][E1_TOK];
    __shared__ int   s_tk2[2][E2_TOK];
    __shared__ float s_part[4][TILE_M];

    const int tid  = threadIdx.x;
    const int wid  = tid >> 5;
    const int lane = tid & 31;
    const float4* numf4 = reinterpret_cast<const float4*>(numf);
    const long nF4 = (long)n * 4;

    // ---- B fragments (fp16), built once (bias folded at k==36) ----
    uint32_t B[4][5];
    float w2r[4][2];
    {
        const int nsub = lane >> 2;
        const int ksub = (lane & 3) * 2;
        #pragma unroll
        for (int j = 0; j < 4; j++) {
            int nn = wid * 32 + j * 8 + nsub;
            #pragma unroll
            for (int p = 0; p < 5; p++) {
                int k0 = p * 8 + ksub;
                float wv0 = (k0     < DIN) ? W1[k0 * H + nn]     : ((k0     == DIN) ? b1[nn] : 0.0f);
                float wv1 = (k0 + 1 < DIN) ? W1[(k0 + 1)*H + nn] : ((k0 + 1 == DIN) ? b1[nn] : 0.0f);
                B[j][p] = h2pair(wv0, wv1);
            }
            int nc = wid * 32 + j * 8 + (lane & 3) * 2;
            w2r[j][0] = W2[nc];
            w2r[j][1] = W2[nc + 1];
        }
    }
    const float b2v = b2[0];
    const int ar = lane >> 2;
    const int kb = lane & 3;

    // ===== Prologue =====
    const int tile0 = blockIdx.x;
    {
        int r0g = tile0 * TILE_M;
        for (int r = tid; r < E1_TOK; r += THREADS) {
            int g = r0g - CS1 + r;
            s_tk1[0][r] = (g >= 0 && g < n) ? t1[g] : -1;
        }
        for (int r = tid; r < E2_TOK; r += THREADS) {
            int g = r0g - CS2 + r;
            s_tk2[0][r] = (g >= 0 && g < n) ? t2[g] : -1;
        }
    }
    __syncthreads();
    // pair-lane gather for t0
    #pragma unroll
    for (int u = 0; u < 5; u++) {
        int row = u * 64 + wid * 16 + (lane >> 1);
        uint4 v = make_uint4(0u, 0u, 0u, 0u);
        if (row < NROWS) {
            int tok = (row < E1_TOK) ? s_tk1[0][row] : s_tk2[0][row - E1_TOK];
            const uint4* tab = (row < E1_TOK) ? g_T1h : g_T2h;
            if (tok >= 0) v = __ldg(tab + tok * 2 + (lane & 1));
        }
        uint32_t w4 = __shfl_down_sync(0xFFFFFFFF, v.x, 1);
        if (((lane & 1) == 0) && row < NROWS) {
            uint32_t* d = (row < E1_TOK) ? &s_e1[row * 5] : &s_e2[(row - E1_TOK) * 5];
            d[0] = v.x; d[1] = v.y; d[2] = v.z; d[3] = v.w; d[4] = w4;
        }
    }
    // tokens(t1) -> buf1
    {
        int nt = tile0 + gridDim.x;
        if (nt < nTiles) {
            int r0g = nt * TILE_M;
            for (int r = tid; r < E1_TOK; r += THREADS) {
                int g = r0g - CS1 + r;
                s_tk1[1][r] = (g >= 0 && g < n) ? t1[g] : -1;
            }
            for (int r = tid; r < E2_TOK; r += THREADS) {
                int g = r0g - CS2 + r;
                s_tk2[1][r] = (g >= 0 && g < n) ? t2[g] : -1;
            }
        }
    }
    // numeric(t0) -> planes 10..17 (coalesced)
    #pragma unroll
    for (int u = 0; u < 4; u++) {
        int e = u * THREADS + tid;
        long gf4 = (long)tile0 * (TILE_M * 4) + e;
        float4 v = (gf4 < nF4) ? __ldg(numf4 + gf4) : make_float4(0.f, 0.f, 0.f, 0.f);
        int r = e >> 2, q = e & 3;
        s_A[(10 + 2*q) * PW + r] = h2pair(v.x, v.y);
        s_A[(11 + 2*q) * PW + r] = h2pair(v.z, v.w);
    }
    // bias planes (constant across tiles)
    s_A[18 * PW + tid] = 0x00003C00u;
    s_A[19 * PW + tid] = 0u;
    __syncthreads();

    int p = 0;   // s_tk[p^1] holds tokens(t+1)
    for (int tile = tile0; tile < nTiles; tile += gridDim.x) {
        const int i = tile * TILE_M + tid;

        // ===== Phase A: x-build e-planes 0..9 =====
        {
            int lo1 = max(i - CS1, 0), hi1 = min(i + CS1 + 1, n);
            int lo2 = max(i - CS2, 0), hi2 = min(i + CS2 + 1, n);
            float inv1 = __fdividef(1.0f, (float)max(hi1 - lo1, 1));
            float inv2 = __fdividef(1.0f, (float)max(hi2 - lo2, 1));

            #pragma unroll
            for (int q = 0; q < 5; q++) {
                float sa = 0.0f, sb = 0.0f;
                #pragma unroll
                for (int w = 0; w < 3; w++) {
                    float2 v = __half22float2(*reinterpret_cast<const __half2*>(&s_e1[(tid + w) * 5 + q]));
                    sa += v.x; sb += v.y;
                }
                s_A[q * PW + tid] = h2pair(sa * inv1, sb * inv1);
            }
            #pragma unroll
            for (int q = 0; q < 5; q++) {
                float sa = 0.0f, sb = 0.0f;
                #pragma unroll
                for (int w = 0; w < 7; w++) {
                    float2 v = __half22float2(*reinterpret_cast<const __half2*>(&s_e2[(tid + w) * 5 + q]));
                    sa += v.x; sb += v.y;
                }
                s_A[(5 + q) * PW + tid] = h2pair(sa * inv2, sb * inv2);
            }
        }
        __syncthreads();

        // ===== Phase B: prefetch(t+1) + MMA + e-STS =====
        const int nt1 = tile + gridDim.x;
        const int nt2 = nt1 + gridDim.x;
        const bool hasN1 = nt1 < nTiles;
        const bool hasN2 = nt2 < nTiles;

        // pair-lane gather LDGs for t+1
        uint4 pv[5];
        if (hasN1) {
            #pragma unroll
            for (int u = 0; u < 5; u++) {
                int row = u * 64 + wid * 16 + (lane >> 1);
                pv[u] = make_uint4(0u, 0u, 0u, 0u);
                if (row < NROWS) {
                    int tok = (row < E1_TOK) ? s_tk1[p ^ 1][row] : s_tk2[p ^ 1][row - E1_TOK];
                    const uint4* tab = (row < E1_TOK) ? g_T1h : g_T2h;
                    if (tok >= 0) pv[u] = __ldg(tab + tok * 2 + (lane & 1));
                }
            }
        }
        // numeric(t+1) coalesced prefetch
        float4 nv[4];
        if (hasN1) {
            #pragma unroll
            for (int u = 0; u < 4; u++) {
                int e = u * THREADS + tid;
                long gf4 = (long)nt1 * (TILE_M * 4) + e;
                nv[u] = (gf4 < nF4) ? __ldg(numf4 + gf4) : make_float4(0.f, 0.f, 0.f, 0.f);
            }
        }
        // tokens(t+2) prefetch
        int pt1a = -1, pt1b = -1, pt2a = -1, pt2b = -1;
        if (hasN2) {
            int nr0 = nt2 * TILE_M;
            int g = nr0 - CS1 + tid;
            pt1a = (g >= 0 && g < n) ? t1[g] : -1;
            if (tid < E1_TOK - TILE_M) {
                g = nr0 - CS1 + TILE_M + tid;
                pt1b = (g >= 0 && g < n) ? t1[g] : -1;
            }
            g = nr0 - CS2 + tid;
            pt2a = (g >= 0 && g < n) ? t2[g] : -1;
            if (tid < E2_TOK - TILE_M) {
                g = nr0 - CS2 + TILE_M + tid;
                pt2b = (g >= 0 && g < n) ? t2[g] : -1;
            }
        }

        // ---- MMA over 8 m-tiles ----
        #pragma unroll
        for (int mt = 0; mt < 8; mt++) {
            float Dacc[4][4];
            #pragma unroll
            for (int j = 0; j < 4; j++) {
                Dacc[j][0] = 0.f; Dacc[j][1] = 0.f; Dacc[j][2] = 0.f; Dacc[j][3] = 0.f;
            }
            const int rb = mt * 16;
            const int ra = rb + ar;

            #pragma unroll
            for (int s = 0; s < 2; s++) {
                const int kw = s * 8 + kb;
                uint32_t a0 = s_A[kw * PW + ra];
                uint32_t a1 = s_A[kw * PW + ra + 8];
                uint32_t a2 = s_A[(kw + 4) * PW + ra];
                uint32_t a3 = s_A[(kw + 4) * PW + ra + 8];
                #pragma unroll
                for (int j = 0; j < 4; j++)
                    mma16(Dacc[j], a0, a1, a2, a3, B[j][2*s], B[j][2*s + 1]);
            }
            {
                const int kw = 16 + kb;
                uint32_t a0 = s_A[kw * PW + ra];
                uint32_t a1 = s_A[kw * PW + ra + 8];
                #pragma unroll
                for (int j = 0; j < 4; j++) mma8(Dacc[j], a0, a1, B[j][4]);
            }

            float p0 = 0.0f, p1 = 0.0f;
            #pragma unroll
            for (int j = 0; j < 4; j++) {
                p0 = fmaf(fmaxf(Dacc[j][0], 0.f), w2r[j][0], p0);
                p0 = fmaf(fmaxf(Dacc[j][1], 0.f), w2r[j][1], p0);
                p1 = fmaf(fmaxf(Dacc[j][2], 0.f), w2r[j][0], p1);
                p1 = fmaf(fmaxf(Dacc[j][3], 0.f), w2r[j][1], p1);
            }
            p0 += __shfl_xor_sync(0xFFFFFFFF, p0, 1);
            p0 += __shfl_xor_sync(0xFFFFFFFF, p0, 2);
            p1 += __shfl_xor_sync(0xFFFFFFFF, p1, 1);
            p1 += __shfl_xor_sync(0xFFFFFFFF, p1, 2);
            if ((lane & 3) == 0) {
                s_part[wid][rb + ar]     = p0;
                s_part[wid][rb + ar + 8] = p1;
            }
        }

        // ---- e-gather STS (s_e only: not read during MMA) ----
        if (hasN1) {
            #pragma unroll
            for (int u = 0; u < 5; u++) {
                int row = u * 64 + wid * 16 + (lane >> 1);
                uint32_t w4 = __shfl_down_sync(0xFFFFFFFF, pv[u].x, 1);
                if (((lane & 1) == 0) && row < NROWS) {
                    uint32_t* d = (row < E1_TOK) ? &s_e1[row * 5] : &s_e2[(row - E1_TOK) * 5];
                    d[0] = pv[u].x; d[1] = pv[u].y; d[2] = pv[u].z; d[3] = pv[u].w; d[4] = w4;
                }
            }
        }
        __syncthreads();   // MMA done chip-wide in block; s_part visible

        // ===== Phase C: out + numeric planes (t+1) + token stash (t+2) =====
        if (i < n) {
            float s = s_part[0][tid] + s_part[1][tid] + s_part[2][tid] + s_part[3][tid] + b2v;
            out[i] = __fdividef(1.0f, 1.0f + __expf(-s));
        }
        if (hasN1) {
            #pragma unroll
            for (int u = 0; u < 4; u++) {
                int e = u * THREADS + tid;
                int r = e >> 2, q = e & 3;
                s_A[(10 + 2*q) * PW + r] = h2pair(nv[u].x, nv[u].y);
                s_A[(11 + 2*q) * PW + r] = h2pair(nv[u].z, nv[u].w);
            }
        }
        if (hasN2) {
            s_tk1[p][tid] = pt1a;
            if (tid < E1_TOK - TILE_M) s_tk1[p][TILE_M + tid] = pt1b;
            s_tk2[p][tid] = pt2a;
            if (tid < E2_TOK - TILE_M) s_tk2[p][TILE_M + tid] = pt2b;
        }
        __syncthreads();
        p ^= 1;
    }
}

extern "C" void kernel_launch(void* const* d_in, const int* in_sizes, int n_in,
                              void* d_out, int out_size) {
    const int*   t1   = (const int*)d_in[0];
    const int*   t2   = (const int*)d_in[1];
    const float* numf = (const float*)d_in[2];
    const float* T1   = (const float*)d_in[3];
    const float* T2   = (const float*)d_in[4];
    const float* W1   = (const float*)d_in[5];
    const float* b1   = (const float*)d_in[6];
    const float* W2   = (const float*)d_in[7];
    const float* b2   = (const float*)d_in[8];
    float* out = (float*)d_out;

    int n = in_sizes[0];
    int vocab = in_sizes[3] / D;
    if (vocab > VOCAB_MAX) vocab = VOCAB_MAX;
    int nTiles = (n + TILE_M - 1) / TILE_M;

    int cblocks = (vocab * 2 + 255) / 256;
    convert_tables_kernel<<<cblocks, 256>>>(T1, T2, vocab);

    int grid = 148 * 6;
    if (grid > nTiles) grid = nTiles;
    wordemb_wf_kernel<<<grid, THREADS>>>(t1, t2, numf, W1, b1, W2, b2, out, n, nTiles);
}

// round 12
// speedup vs baseline: 1.1310x; 1.1310x over previous
#include <cuda_runtime.h>
#include <cuda_fp16.h>
#include <cstdint>
#include <math.h>

#define D        10
#define NUMF     16
#define DIN      36
#define H        128
#define CS1      1
#define CS2      3
#define TILE_M   128
#define THREADS  128

#define E1_TOK (TILE_M + 2*CS1)   // 130
#define E2_TOK (TILE_M + 2*CS2)   // 134
#define KW     20
#define PW     136                 // plane stride: 136 % 32 == 8 -> conflict-free frags
#define VOCAB_MAX 65536

// fp16 tables: row = 16 halves (10 used) = 32B
__device__ uint4 g_T1h[VOCAB_MAX * 2];
__device__ uint4 g_T2h[VOCAB_MAX * 2];

__device__ __forceinline__ uint32_t h2pair(float a, float b) {
    __half2 h = __floats2half2_rn(a, b);
    return *reinterpret_cast<uint32_t*>(&h);
}

__global__ void convert_tables_kernel(const float* __restrict__ T1,
                                      const float* __restrict__ T2, int vocab) {
    int idx = blockIdx.x * blockDim.x + threadIdx.x;
    int total = vocab * 2;
    for (int e = idx; e < total; e += gridDim.x * blockDim.x) {
        int r = e >> 1, hf = e & 1;
        const float* r1 = T1 + r * D;
        const float* r2 = T2 + r * D;
        uint4 v1, v2;
        if (hf == 0) {
            v1.x = h2pair(r1[0], r1[1]); v1.y = h2pair(r1[2], r1[3]);
            v1.z = h2pair(r1[4], r1[5]); v1.w = h2pair(r1[6], r1[7]);
            v2.x = h2pair(r2[0], r2[1]); v2.y = h2pair(r2[2], r2[3]);
            v2.z = h2pair(r2[4], r2[5]); v2.w = h2pair(r2[6], r2[7]);
        } else {
            v1.x = h2pair(r1[8], r1[9]); v1.y = 0u; v1.z = 0u; v1.w = 0u;
            v2.x = h2pair(r2[8], r2[9]); v2.y = 0u; v2.z = 0u; v2.w = 0u;
        }
        g_T1h[e] = v1;
        g_T2h[e] = v2;
    }
}

__device__ __forceinline__ void load_rowh(const uint4* __restrict__ tab, int tok,
                                          uint32_t o[5]) {
    if (tok >= 0) {
        uint4 a = __ldg(tab + tok * 2);
        uint32_t b = __ldg(reinterpret_cast<const uint32_t*>(tab + tok * 2 + 1));
        o[0] = a.x; o[1] = a.y; o[2] = a.z; o[3] = a.w; o[4] = b;
    } else {
        o[0] = 0u; o[1] = 0u; o[2] = 0u; o[3] = 0u; o[4] = 0u;
    }
}
__device__ __forceinline__ void store_rowh(uint32_t* s_e, int r, const uint32_t o[5]) {
    #pragma unroll
    for (int q = 0; q < 5; q++) s_e[r * 5 + q] = o[q];
}

__device__ __forceinline__ void mma16(float d[4],
                                      uint32_t a0, uint32_t a1, uint32_t a2, uint32_t a3,
                                      uint32_t b0, uint32_t b1) {
    asm volatile(
        "mma.sync.aligned.m16n8k16.row.col.f32.f16.f16.f32 "
        "{%0,%1,%2,%3}, {%4,%5,%6,%7}, {%8,%9}, {%0,%1,%2,%3};"
        : "+f"(d[0]), "+f"(d[1]), "+f"(d[2]), "+f"(d[3])
        : "r"(a0), "r"(a1), "r"(a2), "r"(a3), "r"(b0), "r"(b1));
}
__device__ __forceinline__ void mma8(float d[4], uint32_t a0, uint32_t a1, uint32_t b0) {
    asm volatile(
        "mma.sync.aligned.m16n8k8.row.col.f32.f16.f16.f32 "
        "{%0,%1,%2,%3}, {%4,%5}, {%6}, {%0,%1,%2,%3};"
        : "+f"(d[0]), "+f"(d[1]), "+f"(d[2]), "+f"(d[3])
        : "r"(a0), "r"(a1), "r"(b0));
}

__global__ __launch_bounds__(THREADS, 6)
void wordemb_h2_kernel(
    const int*   __restrict__ t1,
    const int*   __restrict__ t2,
    const float* __restrict__ numf,
    const float* __restrict__ W1,
    const float* __restrict__ b1,
    const float* __restrict__ W2,
    const float* __restrict__ b2,
    float* __restrict__ out,
    int n, int nTiles)
{
    __shared__ uint32_t s_A[KW * PW];
    __shared__ uint32_t s_e1[E1_TOK * 5];   // half2 words, stride 5 (coprime 32)
    __shared__ uint32_t s_e2[E2_TOK * 5];
    __shared__ int   s_tk1[2][E1_TOK];
    __shared__ int   s_tk2[2][E2_TOK];
    __shared__ float s_part[4][TILE_M];

    const int tid  = threadIdx.x;
    const int wid  = tid >> 5;
    const int lane = tid & 31;
    const float4* numf4 = reinterpret_cast<const float4*>(numf);
    const long nF4 = (long)n * 4;

    // ---- B fragments (fp16), built once (bias folded at k==36) ----
    uint32_t B[4][5];
    float w2r[4][2];
    {
        const int nsub = lane >> 2;
        const int ksub = (lane & 3) * 2;
        #pragma unroll
        for (int j = 0; j < 4; j++) {
            int nn = wid * 32 + j * 8 + nsub;
            #pragma unroll
            for (int p = 0; p < 5; p++) {
                int k0 = p * 8 + ksub;
                float wv0 = (k0     < DIN) ? W1[k0 * H + nn]     : ((k0     == DIN) ? b1[nn] : 0.0f);
                float wv1 = (k0 + 1 < DIN) ? W1[(k0 + 1)*H + nn] : ((k0 + 1 == DIN) ? b1[nn] : 0.0f);
                B[j][p] = h2pair(wv0, wv1);
            }
            int nc = wid * 32 + j * 8 + (lane & 3) * 2;
            w2r[j][0] = W2[nc];
            w2r[j][1] = W2[nc + 1];
        }
    }
    const float b2v = b2[0];
    const int ar = lane >> 2;
    const int kb = lane & 3;

    const __half2* e1h = reinterpret_cast<const __half2*>(s_e1);
    const __half2* e2h = reinterpret_cast<const __half2*>(s_e2);
    __half2* Ah = reinterpret_cast<__half2*>(s_A);

    // ===== Prologue: tokens(t0); gather(t0); tokens(t1); numeric(t0); bias =====
    const int tile0 = blockIdx.x;
    {
        int r0g = tile0 * TILE_M;
        for (int r = tid; r < E1_TOK; r += THREADS) {
            int g = r0g - CS1 + r;
            s_tk1[0][r] = (g >= 0 && g < n) ? t1[g] : -1;
        }
        for (int r = tid; r < E2_TOK; r += THREADS) {
            int g = r0g - CS2 + r;
            s_tk2[0][r] = (g >= 0 && g < n) ? t2[g] : -1;
        }
    }
    __syncthreads();
    for (int r = tid; r < E1_TOK; r += THREADS) {
        uint32_t o[5];
        load_rowh(g_T1h, s_tk1[0][r], o);
        store_rowh(s_e1, r, o);
    }
    for (int r = tid; r < E2_TOK; r += THREADS) {
        uint32_t o[5];
        load_rowh(g_T2h, s_tk2[0][r], o);
        store_rowh(s_e2, r, o);
    }
    {
        int nt = tile0 + gridDim.x;
        if (nt < nTiles) {
            int r0g = nt * TILE_M;
            for (int r = tid; r < E1_TOK; r += THREADS) {
                int g = r0g - CS1 + r;
                s_tk1[1][r] = (g >= 0 && g < n) ? t1[g] : -1;
            }
            for (int r = tid; r < E2_TOK; r += THREADS) {
                int g = r0g - CS2 + r;
                s_tk2[1][r] = (g >= 0 && g < n) ? t2[g] : -1;
            }
        }
    }
    // numeric(t0) -> planes 10..17 (coalesced)
    #pragma unroll
    for (int u = 0; u < 4; u++) {
        int e = u * THREADS + tid;
        long gf4 = (long)tile0 * (TILE_M * 4) + e;
        float4 v = (gf4 < nF4) ? __ldg(numf4 + gf4) : make_float4(0.f, 0.f, 0.f, 0.f);
        int r = e >> 2, q = e & 3;
        s_A[(10 + 2*q) * PW + r] = h2pair(v.x, v.y);
        s_A[(11 + 2*q) * PW + r] = h2pair(v.z, v.w);
    }
    s_A[18 * PW + tid] = 0x00003C00u;   // (fp16 1.0, 0.0) bias channel
    s_A[19 * PW + tid] = 0u;
    __syncthreads();

    int p = 0;   // s_tk[p^1] holds tokens(t+1)
    for (int tile = tile0; tile < nTiles; tile += gridDim.x) {
        const int i = tile * TILE_M + tid;

        // ===== Phase A: x-build (half2 arithmetic) -> e-planes 0..9 =====
        {
            int lo1 = max(i - CS1, 0), hi1 = min(i + CS1 + 1, n);
            int lo2 = max(i - CS2, 0), hi2 = min(i + CS2 + 1, n);
            __half2 inv1 = __float2half2_rn(__fdividef(1.0f, (float)max(hi1 - lo1, 1)));
            __half2 inv2 = __float2half2_rn(__fdividef(1.0f, (float)max(hi2 - lo2, 1)));

            #pragma unroll
            for (int q = 0; q < 5; q++) {        // e1: window of 3
                __half2 a = e1h[(tid + 0) * 5 + q];
                __half2 b = e1h[(tid + 1) * 5 + q];
                __half2 c = e1h[(tid + 2) * 5 + q];
                Ah[q * PW + tid] = __hmul2(__hadd2(__hadd2(a, b), c), inv1);
            }
            #pragma unroll
            for (int q = 0; q < 5; q++) {        // e2: window of 7 (tree sum)
                __half2 v0 = e2h[(tid + 0) * 5 + q];
                __half2 v1 = e2h[(tid + 1) * 5 + q];
                __half2 v2 = e2h[(tid + 2) * 5 + q];
                __half2 v3 = e2h[(tid + 3) * 5 + q];
                __half2 v4 = e2h[(tid + 4) * 5 + q];
                __half2 v5 = e2h[(tid + 5) * 5 + q];
                __half2 v6 = e2h[(tid + 6) * 5 + q];
                __half2 s = __hadd2(__hadd2(__hadd2(v0, v1), __hadd2(v2, v3)),
                                    __hadd2(__hadd2(v4, v5), v6));
                Ah[(5 + q) * PW + tid] = __hmul2(s, inv2);
            }
        }
        __syncthreads();

        // ===== Phase B: prefetch(t+1) + MMA =====
        const int nt1 = tile + gridDim.x;
        const int nt2 = nt1 + gridDim.x;
        const bool hasN1 = nt1 < nTiles;
        const bool hasN2 = nt2 < nTiles;

        uint32_t pg1a[5], pg1b[5], pg2a[5], pg2b[5];
        if (hasN1) {
            load_rowh(g_T1h, s_tk1[p ^ 1][tid], pg1a);
            if (tid < E1_TOK - TILE_M) load_rowh(g_T1h, s_tk1[p ^ 1][TILE_M + tid], pg1b);
            load_rowh(g_T2h, s_tk2[p ^ 1][tid], pg2a);
            if (tid < E2_TOK - TILE_M) load_rowh(g_T2h, s_tk2[p ^ 1][TILE_M + tid], pg2b);
        }
        uint32_t nvh[8];
        if (hasN1) {
            #pragma unroll
            for (int u = 0; u < 4; u++) {
                int e = u * THREADS + tid;
                long gf4 = (long)nt1 * (TILE_M * 4) + e;
                float4 v = (gf4 < nF4) ? __ldg(numf4 + gf4) : make_float4(0.f, 0.f, 0.f, 0.f);
                nvh[2*u]     = h2pair(v.x, v.y);
                nvh[2*u + 1] = h2pair(v.z, v.w);
            }
        }
        int pt1a = -1, pt1b = -1, pt2a = -1, pt2b = -1;
        if (hasN2) {
            int nr0 = nt2 * TILE_M;
            int g = nr0 - CS1 + tid;
            pt1a = (g >= 0 && g < n) ? t1[g] : -1;
            if (tid < E1_TOK - TILE_M) {
                g = nr0 - CS1 + TILE_M + tid;
                pt1b = (g >= 0 && g < n) ? t1[g] : -1;
            }
            g = nr0 - CS2 + tid;
            pt2a = (g >= 0 && g < n) ? t2[g] : -1;
            if (tid < E2_TOK - TILE_M) {
                g = nr0 - CS2 + TILE_M + tid;
                pt2b = (g >= 0 && g < n) ? t2[g] : -1;
            }
        }

        // ---- MMA over 8 m-tiles (fp16 single product) ----
        #pragma unroll
        for (int mt = 0; mt < 8; mt++) {
            float Dacc[4][4];
            #pragma unroll
            for (int j = 0; j < 4; j++) {
                Dacc[j][0] = 0.f; Dacc[j][1] = 0.f; Dacc[j][2] = 0.f; Dacc[j][3] = 0.f;
            }
            const int rb = mt * 16;
            const int ra = rb + ar;

            #pragma unroll
            for (int s = 0; s < 2; s++) {
                const int kw = s * 8 + kb;
                uint32_t a0 = s_A[kw * PW + ra];
                uint32_t a1 = s_A[kw * PW + ra + 8];
                uint32_t a2 = s_A[(kw + 4) * PW + ra];
                uint32_t a3 = s_A[(kw + 4) * PW + ra + 8];
                #pragma unroll
                for (int j = 0; j < 4; j++)
                    mma16(Dacc[j], a0, a1, a2, a3, B[j][2*s], B[j][2*s + 1]);
            }
            {
                const int kw = 16 + kb;
                uint32_t a0 = s_A[kw * PW + ra];
                uint32_t a1 = s_A[kw * PW + ra + 8];
                #pragma unroll
                for (int j = 0; j < 4; j++) mma8(Dacc[j], a0, a1, B[j][4]);
            }

            float p0 = 0.0f, p1 = 0.0f;
            #pragma unroll
            for (int j = 0; j < 4; j++) {
                p0 = fmaf(fmaxf(Dacc[j][0], 0.f), w2r[j][0], p0);
                p0 = fmaf(fmaxf(Dacc[j][1], 0.f), w2r[j][1], p0);
                p1 = fmaf(fmaxf(Dacc[j][2], 0.f), w2r[j][0], p1);
                p1 = fmaf(fmaxf(Dacc[j][3], 0.f), w2r[j][1], p1);
            }
            p0 += __shfl_xor_sync(0xFFFFFFFF, p0, 1);
            p0 += __shfl_xor_sync(0xFFFFFFFF, p0, 2);
            p1 += __shfl_xor_sync(0xFFFFFFFF, p1, 1);
            p1 += __shfl_xor_sync(0xFFFFFFFF, p1, 2);
            if ((lane & 3) == 0) {
                s_part[wid][rb + ar]     = p0;
                s_part[wid][rb + ar + 8] = p1;
            }
        }

        // ---- write prefetched e-rows to s_e (not read during MMA) ----
        if (hasN1) {
            store_rowh(s_e1, tid, pg1a);
            if (tid < E1_TOK - TILE_M) store_rowh(s_e1, TILE_M + tid, pg1b);
            store_rowh(s_e2, tid, pg2a);
            if (tid < E2_TOK - TILE_M) store_rowh(s_e2, TILE_M + tid, pg2b);
        }
        __syncthreads();

        // ===== Phase C: out + numeric planes(t+1) + token stash(t+2) =====
        if (i < n) {
            float s = s_part[0][tid] + s_part[1][tid] + s_part[2][tid] + s_part[3][tid] + b2v;
            out[i] = __fdividef(1.0f, 1.0f + __expf(-s));
        }
        if (hasN1) {
            #pragma unroll
            for (int u = 0; u < 4; u++) {
                int e = u * THREADS + tid;
                int r = e >> 2, q = e & 3;
                s_A[(10 + 2*q) * PW + r] = nvh[2*u];
                s_A[(11 + 2*q) * PW + r] = nvh[2*u + 1];
            }
        }
        if (hasN2) {
            s_tk1[p][tid] = pt1a;
            if (tid < E1_TOK - TILE_M) s_tk1[p][TILE_M + tid] = pt1b;
            s_tk2[p][tid] = pt2a;
            if (tid < E2_TOK - TILE_M) s_tk2[p][TILE_M + tid] = pt2b;
        }
        __syncthreads();
        p ^= 1;
    }
}

extern "C" void kernel_launch(void* const* d_in, const int* in_sizes, int n_in,
                              void* d_out, int out_size) {
    const int*   t1   = (const int*)d_in[0];
    const int*   t2   = (const int*)d_in[1];
    const float* numf = (const float*)d_in[2];
    const float* T1   = (const float*)d_in[3];
    const float* T2   = (const float*)d_in[4];
    const float* W1   = (const float*)d_in[5];
    const float* b1   = (const float*)d_in[6];
    const float* W2   = (const float*)d_in[7];
    const float* b2   = (const float*)d_in[8];
    float* out = (float*)d_out;

    int n = in_sizes[0];
    int vocab = in_sizes[3] / D;
    if (vocab > VOCAB_MAX) vocab = VOCAB_MAX;
    int nTiles = (n + TILE_M - 1) / TILE_M;

    int cblocks = (vocab * 2 + 255) / 256;
    convert_tables_kernel<<<cblocks, 256>>>(T1, T2, vocab);

    int grid = 148 * 6;
    if (grid > nTiles) grid = nTiles;
    wordemb_h2_kernel<<<grid, THREADS>>>(t1, t2, numf, W1, b1, W2, b2, out, n, nTiles);
}